// round 5
// baseline (speedup 1.0000x reference)
#include <cuda_runtime.h>
#include <cuda_bf16.h>
#include <math.h>
#include <cstdint>

#define Bn 16384
#define Dn 1024
#define Kn 512
#define Ln 128
#define Hn 64

#define MTILE 128
#define NTILE 128
#define DK    128            // fp8 elems per chunk (128B rows)
#define NCHUNK (Dn / DK)     // 8

#define L2E 1.4426950408889634f
#define SCALE 16.0f
#define SINV (2.0f * L2E / (SCALE * SCALE))

// ---------------- scratch ----------------
__device__ uint8_t g_phi8[Kn * Dn];        // 0.5 MB (e4m3, scaled by 16)
__device__ uint8_t g_x8[Bn * Dn];          // 16 MB  (e4m3, scaled by 16)
__device__ float g_phinorm[Kn];
__device__ float g_xnorm[Bn];
__device__ float g_colsum[Bn];
__device__ int   g_cnt[Bn / NTILE];        // per-b-slice completion counters

// ---------------- helpers ----------------
__device__ __forceinline__ uint32_t smem_u32(const void* p) {
    uint32_t a;
    asm("{ .reg .u64 t; cvta.to.shared.u64 t, %1; cvt.u32.u64 %0, t; }" : "=r"(a) : "l"(p));
    return a;
}

#define LDSM4(r0, r1, r2, r3, addr) \
    asm volatile("ldmatrix.sync.aligned.m8n8.x4.shared.b16 {%0,%1,%2,%3}, [%4];" \
                 : "=r"(r0), "=r"(r1), "=r"(r2), "=r"(r3) : "r"(addr))

#define MMA16832(d, a, b0, b1) \
    asm volatile("mma.sync.aligned.m16n8k32.row.col.f32.e4m3.e4m3.f32 " \
                 "{%0,%1,%2,%3}, {%4,%5,%6,%7}, {%8,%9}, {%0,%1,%2,%3};" \
                 : "+f"((d)[0]), "+f"((d)[1]), "+f"((d)[2]), "+f"((d)[3]) \
                 : "r"((a)[0]), "r"((a)[1]), "r"((a)[2]), "r"((a)[3]), \
                   "r"(b0), "r"(b1))

#define CP16(dst, src) \
    asm volatile("cp.async.cg.shared.global [%0], [%1], 16;" :: "r"(dst), "l"(src))
#define CP_COMMIT() asm volatile("cp.async.commit_group;" ::: "memory")
#define CP_WAIT0()  asm volatile("cp.async.wait_group 0;" ::: "memory")

// pack 4 floats -> 4 e4m3 bytes (e0 in lowest byte)
__device__ __forceinline__ uint32_t pack_e4m3x4(float e0, float e1, float e2, float e3) {
    uint16_t lo, hi;
    asm("cvt.rn.satfinite.e4m3x2.f32 %0, %1, %2;" : "=h"(lo) : "f"(e1), "f"(e0));
    asm("cvt.rn.satfinite.e4m3x2.f32 %0, %1, %2;" : "=h"(hi) : "f"(e3), "f"(e2));
    return (uint32_t)lo | ((uint32_t)hi << 16);
}

// fast 2^t, FFMA-only (no MUFU). t clamped below; deg-4 poly on [-0.5,0.5]
__device__ __forceinline__ float exp2_fast(float t) {
    t = fmaxf(t, -126.0f);
    const int   i = __float2int_rn(t);
    const float f = t - (float)i;
    float p = fmaf(0.0096181291f, f, 0.0555041087f);
    p = fmaf(p, f, 0.2402265069f);
    p = fmaf(p, f, 0.6931471806f);
    p = fmaf(p, f, 1.0f);
    return p * __int_as_float((i + 127) << 23);
}

// ============================================================
// Kernel 1 (prep): blocks [0, Bn) = x convert; [Bn, Bn+Kn) = phi
// ============================================================
__global__ __launch_bounds__(256) void prep_kernel(
    const float* __restrict__ x,  const float* __restrict__ z,
    const float* __restrict__ W1, const float* __restrict__ b1,
    const float* __restrict__ W2, const float* __restrict__ b2,
    float* __restrict__ out)
{
    __shared__ float red[256];
    const int t = threadIdx.x;

    if (blockIdx.x < Bn) {
        // ---- x path: fp32 -> e4m3*16, ||x||^2, init colsum/cnt/out ----
        const int b = blockIdx.x;
        const float4 v = *reinterpret_cast<const float4*>(x + b * Dn + t * 4);
        *reinterpret_cast<uint32_t*>(g_x8 + b * Dn + t * 4) =
            pack_e4m3x4(v.x * SCALE, v.y * SCALE, v.z * SCALE, v.w * SCALE);

        red[t] = v.x * v.x + v.y * v.y + v.z * v.z + v.w * v.w;
        __syncthreads();
        for (int s = 128; s > 0; s >>= 1) {
            if (t < s) red[t] += red[t + s];
            __syncthreads();
        }
        if (t == 0) {
            g_xnorm[b] = red[0];
            g_colsum[b] = 0.0f;
            if (b < Bn / NTILE) g_cnt[b] = 0;
            if (b == 0) out[0] = 0.0f;
        }
    } else {
        // ---- phi path: ReLU(z@W1+b1)@W2+b2, norm, e4m3*16 ----
        __shared__ float zrow[Ln];
        __shared__ float hidden[Hn];
        const int k = blockIdx.x - Bn;

        if (t < Ln) zrow[t] = z[k * Ln + t];
        __syncthreads();

        if (t < Hn) {
            float acc = b1[t];
            #pragma unroll 8
            for (int l = 0; l < Ln; l++)
                acc = fmaf(zrow[l], W1[l * Hn + t], acc);
            hidden[t] = fmaxf(acc, 0.0f);
        }
        __syncthreads();

        const int d0 = t * 4;
        float4 acc = make_float4(b2[d0], b2[d0 + 1], b2[d0 + 2], b2[d0 + 3]);
        #pragma unroll 8
        for (int h = 0; h < Hn; h++) {
            const float hv = hidden[h];
            const float4 w = *reinterpret_cast<const float4*>(W2 + h * Dn + d0);
            acc.x = fmaf(hv, w.x, acc.x);
            acc.y = fmaf(hv, w.y, acc.y);
            acc.z = fmaf(hv, w.z, acc.z);
            acc.w = fmaf(hv, w.w, acc.w);
        }
        *reinterpret_cast<uint32_t*>(g_phi8 + k * Dn + d0) =
            pack_e4m3x4(acc.x * SCALE, acc.y * SCALE, acc.z * SCALE, acc.w * SCALE);

        red[t] = acc.x * acc.x + acc.y * acc.y + acc.z * acc.z + acc.w * acc.w;
        __syncthreads();
        for (int s = 128; s > 0; s >>= 1) {
            if (t < s) red[t] += red[t + s];
            __syncthreads();
        }
        if (t == 0) g_phinorm[k] = red[0];
    }
}

// ============================================================
// Kernel 2 (main): fp8 mma GEMM 128x128 + fused exp/K-sum epilogue
//                  + last-slice-CTA does the log-mean for its 128 b's
// ============================================================
__global__ __launch_bounds__(256, 2) void main_kernel(float* __restrict__ out)
{
    extern __shared__ char smem[];
    const uint32_t Abase = smem_u32(smem);      // 2 stages x 16KB
    const uint32_t Bbase = Abase + 32768;       // 2 stages x 16KB

    const int t    = threadIdx.x;
    const int lane = t & 31;
    const int wid  = t >> 5;
    const int b_base = blockIdx.x * NTILE;
    const int k_base = blockIdx.y * MTILE;

    const int m_off = (wid & 1) * 64;
    const int n_off = (wid >> 1) * 32;

    const uint8_t* gA = g_phi8 + (uint64_t)k_base * Dn;
    const uint8_t* gB = g_x8   + (uint64_t)b_base * Dn;

    // staging map: 4 x 16B units per array per thread (128 rows x 8 units)
    int srow[4], sgo[4];
    uint32_t soff[4];
    #pragma unroll
    for (int i = 0; i < 4; i++) {
        const int u = t + i * 256;
        const int row = u >> 3;
        const int cg  = u & 7;
        srow[i] = row;
        sgo[i]  = cg * 16;
        soff[i] = (uint32_t)(row * 128 + ((cg ^ (row & 7)) << 4));
    }

    float acc[4][4][4];
    #pragma unroll
    for (int i = 0; i < 4; i++)
        #pragma unroll
        for (int j = 0; j < 4; j++)
            #pragma unroll
            for (int r = 0; r < 4; r++) acc[i][j][r] = 0.0f;

    // prologue: stage chunk 0
    #pragma unroll
    for (int i = 0; i < 4; i++) {
        CP16(Abase + soff[i], gA + srow[i] * Dn + sgo[i]);
        CP16(Bbase + soff[i], gB + srow[i] * Dn + sgo[i]);
    }
    CP_COMMIT();

    for (int c = 0; c < NCHUNK; c++) {
        const int buf = c & 1;
        CP_WAIT0();
        __syncthreads();

        if (c + 1 < NCHUNK) {
            const int nb = (c + 1) & 1;
            const int d0 = (c + 1) * DK;
            #pragma unroll
            for (int i = 0; i < 4; i++) {
                CP16(Abase + (uint32_t)nb * 16384u + soff[i], gA + srow[i] * Dn + d0 + sgo[i]);
                CP16(Bbase + (uint32_t)nb * 16384u + soff[i], gB + srow[i] * Dn + d0 + sgo[i]);
            }
            CP_COMMIT();
        }

        const uint32_t Ab = Abase + (uint32_t)buf * 16384u;
        const uint32_t Bb = Bbase + (uint32_t)buf * 16384u;

        #pragma unroll
        for (int ks = 0; ks < 4; ks++) {        // four k32 steps per 128-elem chunk
            uint32_t a[4][4];
            #pragma unroll
            for (int im = 0; im < 4; im++) {
                const int arow = m_off + im * 16 + (lane & 15);
                const int acg  = ks * 2 + (lane >> 4);
                LDSM4(a[im][0], a[im][1], a[im][2], a[im][3],
                      Ab + (uint32_t)(arow * 128 + ((acg ^ (arow & 7)) << 4)));
            }
            uint32_t b[8];
            #pragma unroll
            for (int in_ = 0; in_ < 2; in_++) {
                const int g    = lane >> 3;
                const int nrow = n_off + in_ * 16 + ((g >> 1) << 3) + (lane & 7);
                const int bcg  = ks * 2 + (g & 1);
                LDSM4(b[in_ * 4 + 0], b[in_ * 4 + 1], b[in_ * 4 + 2], b[in_ * 4 + 3],
                      Bb + (uint32_t)(nrow * 128 + ((bcg ^ (nrow & 7)) << 4)));
            }
            #pragma unroll
            for (int im = 0; im < 4; im++)
                #pragma unroll
                for (int ing = 0; ing < 4; ing++)
                    MMA16832(acc[im][ing], a[im], b[ing * 2], b[ing * 2 + 1]);
        }
    }

    // ---------------- fused epilogue ----------------
    // acc[im][ing][r]: r0,r1: m = im*16+(lane>>2),   n = ing*8+(lane&3)*2+{0,1}
    //                  r2,r3: m = im*16+(lane>>2)+8, same n
    // S_true = acc / (SCALE*SCALE); arg = L2E*(2*S_true - pn - xn)
    float pnl[4], pnh[4];
    #pragma unroll
    for (int im = 0; im < 4; im++) {
        pnl[im] = g_phinorm[k_base + m_off + im * 16 + (lane >> 2)] * L2E;
        pnh[im] = g_phinorm[k_base + m_off + im * 16 + (lane >> 2) + 8] * L2E;
    }
    float xnv[4][2];
    #pragma unroll
    for (int ing = 0; ing < 4; ing++)
        #pragma unroll
        for (int j = 0; j < 2; j++)
            xnv[ing][j] = g_xnorm[b_base + n_off + ing * 8 + (lane & 3) * 2 + j] * L2E;

    float sn[4][2];
    #pragma unroll
    for (int ing = 0; ing < 4; ing++) { sn[ing][0] = 0.0f; sn[ing][1] = 0.0f; }

    #pragma unroll
    for (int im = 0; im < 4; im++) {
        #pragma unroll
        for (int ing = 0; ing < 4; ing++) {
            #pragma unroll
            for (int j = 0; j < 2; j++) {
                const float c1 = pnl[im] + xnv[ing][j];
                const float c2 = pnh[im] + xnv[ing][j];
                sn[ing][j] += exp2_fast(fmaf(SINV, acc[im][ing][j],     -c1));
                sn[ing][j] += exp2_fast(fmaf(SINV, acc[im][ing][2 + j], -c2));
            }
        }
    }
    #pragma unroll
    for (int off = 4; off < 32; off <<= 1)
        #pragma unroll
        for (int ing = 0; ing < 4; ing++)
            #pragma unroll
            for (int j = 0; j < 2; j++)
                sn[ing][j] += __shfl_xor_sync(0xffffffffu, sn[ing][j], off);

    if (lane < 4) {
        #pragma unroll
        for (int ing = 0; ing < 4; ing++)
            #pragma unroll
            for (int j = 0; j < 2; j++)
                atomicAdd(&g_colsum[b_base + n_off + ing * 8 + lane * 2 + j], sn[ing][j]);
    }

    // ---- last-arriving CTA of this b-slice finalizes its 128 columns ----
    __shared__ int is_last;
    __threadfence();
    if (t == 0) {
        const int old = atomicAdd(&g_cnt[blockIdx.x], 1);
        is_last = (old == (Kn / MTILE) - 1);
    }
    __syncthreads();
    if (is_last && t < NTILE) {
        float s = __logf(g_colsum[b_base + t] * (1.0f / (float)Kn) + 1e-9f)
                  * (1.0f / (float)Bn);
        #pragma unroll
        for (int off = 16; off > 0; off >>= 1)
            s += __shfl_xor_sync(0xffffffffu, s, off);
        if (lane == 0) atomicAdd(out, s);
    }
}

// ============================================================
extern "C" void kernel_launch(void* const* d_in, const int* in_sizes, int n_in,
                              void* d_out, int out_size)
{
    const float* x  = (const float*)d_in[0];
    const float* z  = (const float*)d_in[1];
    const float* W1 = (const float*)d_in[2];
    const float* b1 = (const float*)d_in[3];
    const float* W2 = (const float*)d_in[4];
    const float* b2 = (const float*)d_in[5];
    float* out = (float*)d_out;

    static int smem_set = 0;
    if (!smem_set) {
        cudaFuncSetAttribute(main_kernel, cudaFuncAttributeMaxDynamicSharedMemorySize, 65536);
        smem_set = 1;
    }

    prep_kernel<<<Bn + Kn, 256>>>(x, z, W1, b1, W2, b2, out);
    dim3 grid(Bn / NTILE, Kn / MTILE);   // (128, 4)
    main_kernel<<<grid, 256, 65536>>>(out);
}

// round 6
// speedup vs baseline: 1.0880x; 1.0880x over previous
#include <cuda_runtime.h>
#include <cuda_bf16.h>
#include <math.h>
#include <cstdint>

#define Bn 16384
#define Dn 1024
#define Kn 512
#define Ln 128
#define Hn 64

#define MTILE 128
#define NTILE 128
#define DK    128            // fp8 elems per chunk (128B rows)
#define NCHUNK (Dn / DK)     // 8
#define KSLICES 2            // k-slices per CTA (grid.y=2 -> K covered 2*2*128)
#define STAGES 3
#define STAGE_BYTES 32768u   // A(16KB) + B(16KB)

#define L2E 1.4426950408889634f
#define SCALE 16.0f
#define SINV (2.0f * L2E / (SCALE * SCALE))

// ---------------- scratch ----------------
__device__ uint8_t g_phi8[Kn * Dn];        // 0.5 MB (e4m3, scaled by 16)
__device__ uint8_t g_x8[Bn * Dn];          // 16 MB  (e4m3, scaled by 16)
__device__ float g_phinorm[Kn];
__device__ float g_xnorm[Bn];
__device__ float g_colsum[Bn];
__device__ int   g_cnt[Bn / NTILE];

// ---------------- helpers ----------------
__device__ __forceinline__ uint32_t smem_u32(const void* p) {
    uint32_t a;
    asm("{ .reg .u64 t; cvta.to.shared.u64 t, %1; cvt.u32.u64 %0, t; }" : "=r"(a) : "l"(p));
    return a;
}

#define LDSM4(r0, r1, r2, r3, addr) \
    asm volatile("ldmatrix.sync.aligned.m8n8.x4.shared.b16 {%0,%1,%2,%3}, [%4];" \
                 : "=r"(r0), "=r"(r1), "=r"(r2), "=r"(r3) : "r"(addr))

#define MMA16832(d, a, b0, b1) \
    asm volatile("mma.sync.aligned.m16n8k32.row.col.f32.e4m3.e4m3.f32 " \
                 "{%0,%1,%2,%3}, {%4,%5,%6,%7}, {%8,%9}, {%0,%1,%2,%3};" \
                 : "+f"((d)[0]), "+f"((d)[1]), "+f"((d)[2]), "+f"((d)[3]) \
                 : "r"((a)[0]), "r"((a)[1]), "r"((a)[2]), "r"((a)[3]), \
                   "r"(b0), "r"(b1))

#define CP16(dst, src) \
    asm volatile("cp.async.cg.shared.global [%0], [%1], 16;" :: "r"(dst), "l"(src))
#define CP_COMMIT()  asm volatile("cp.async.commit_group;" ::: "memory")
#define CP_WAIT(n)   asm volatile("cp.async.wait_group %0;" :: "n"(n) : "memory")

__device__ __forceinline__ uint32_t pack_e4m3x4(float e0, float e1, float e2, float e3) {
    uint16_t lo, hi;
    asm("cvt.rn.satfinite.e4m3x2.f32 %0, %1, %2;" : "=h"(lo) : "f"(e1), "f"(e0));
    asm("cvt.rn.satfinite.e4m3x2.f32 %0, %1, %2;" : "=h"(hi) : "f"(e3), "f"(e2));
    return (uint32_t)lo | ((uint32_t)hi << 16);
}

// fast 2^t, FFMA-only (no MUFU). deg-4 poly on [-0.5,0.5]
__device__ __forceinline__ float exp2_fast(float t) {
    t = fmaxf(t, -126.0f);
    const int   i = __float2int_rn(t);
    const float f = t - (float)i;
    float p = fmaf(0.0096181291f, f, 0.0555041087f);
    p = fmaf(p, f, 0.2402265069f);
    p = fmaf(p, f, 0.6931471806f);
    p = fmaf(p, f, 1.0f);
    return p * __int_as_float((i + 127) << 23);
}

// ============================================================
// Kernel 1 (prep): blocks [0, 2048) = x (warp per row);
//                  blocks [2048, 2048+Kn) = phi MLP
// ============================================================
__global__ __launch_bounds__(256) void prep_kernel(
    const float* __restrict__ x,  const float* __restrict__ z,
    const float* __restrict__ W1, const float* __restrict__ b1,
    const float* __restrict__ W2, const float* __restrict__ b2,
    float* __restrict__ out)
{
    const int t = threadIdx.x;

    if (blockIdx.x < Bn / 8) {
        // ---- x path: warp per row, no smem ----
        const int lane = t & 31;
        const int b = blockIdx.x * 8 + (t >> 5);
        const float* xr = x + (uint64_t)b * Dn;
        uint8_t* xo = g_x8 + (uint64_t)b * Dn;
        float nrm = 0.0f;
        #pragma unroll
        for (int i = 0; i < 8; i++) {
            const float4 v = *reinterpret_cast<const float4*>(xr + i * 128 + lane * 4);
            *reinterpret_cast<uint32_t*>(xo + i * 128 + lane * 4) =
                pack_e4m3x4(v.x * SCALE, v.y * SCALE, v.z * SCALE, v.w * SCALE);
            nrm = fmaf(v.x, v.x, nrm);
            nrm = fmaf(v.y, v.y, nrm);
            nrm = fmaf(v.z, v.z, nrm);
            nrm = fmaf(v.w, v.w, nrm);
        }
        #pragma unroll
        for (int off = 16; off > 0; off >>= 1)
            nrm += __shfl_xor_sync(0xffffffffu, nrm, off);
        if (lane == 0) {
            g_xnorm[b] = nrm;
            g_colsum[b] = 0.0f;
            if (b < Bn / NTILE) g_cnt[b] = 0;
            if (b == 0) out[0] = 0.0f;
        }
    } else {
        // ---- phi path ----
        __shared__ float zrow[Ln];
        __shared__ float hidden[Hn];
        __shared__ float red[256];
        const int k = blockIdx.x - Bn / 8;

        if (t < Ln) zrow[t] = z[k * Ln + t];
        __syncthreads();

        if (t < Hn) {
            float acc = b1[t];
            #pragma unroll 8
            for (int l = 0; l < Ln; l++)
                acc = fmaf(zrow[l], W1[l * Hn + t], acc);
            hidden[t] = fmaxf(acc, 0.0f);
        }
        __syncthreads();

        const int d0 = t * 4;
        float4 acc = make_float4(b2[d0], b2[d0 + 1], b2[d0 + 2], b2[d0 + 3]);
        #pragma unroll 8
        for (int h = 0; h < Hn; h++) {
            const float hv = hidden[h];
            const float4 w = *reinterpret_cast<const float4*>(W2 + h * Dn + d0);
            acc.x = fmaf(hv, w.x, acc.x);
            acc.y = fmaf(hv, w.y, acc.y);
            acc.z = fmaf(hv, w.z, acc.z);
            acc.w = fmaf(hv, w.w, acc.w);
        }
        *reinterpret_cast<uint32_t*>(g_phi8 + k * Dn + d0) =
            pack_e4m3x4(acc.x * SCALE, acc.y * SCALE, acc.z * SCALE, acc.w * SCALE);

        red[t] = acc.x * acc.x + acc.y * acc.y + acc.z * acc.z + acc.w * acc.w;
        __syncthreads();
        for (int s = 128; s > 0; s >>= 1) {
            if (t < s) red[t] += red[t + s];
            __syncthreads();
        }
        if (t == 0) g_phinorm[k] = red[0];
    }
}

// ============================================================
// Kernel 2 (main): single-wave fp8 mma GEMM, 2 k-slices/CTA,
//   3-stage cp.async pipeline, fused exp epilogue, inline finalize
// ============================================================
__global__ __launch_bounds__(256, 2) void main_kernel(float* __restrict__ out)
{
    extern __shared__ char smem[];
    const uint32_t Sbase = smem_u32(smem);   // STAGES x (A 16KB | B 16KB)

    const int t    = threadIdx.x;
    const int lane = t & 31;
    const int wid  = t >> 5;
    const int b_base = blockIdx.x * NTILE;

    const int m_off = (wid & 1) * 64;
    const int n_off = (wid >> 1) * 32;

    const uint8_t* gB = g_x8 + (uint64_t)b_base * Dn;

    // staging map: 4 x 16B units per array per thread
    int srow[4], sgo[4];
    uint32_t soff[4];
    #pragma unroll
    for (int i = 0; i < 4; i++) {
        const int u = t + i * 256;
        const int row = u >> 3;
        const int cg  = u & 7;
        srow[i] = row;
        sgo[i]  = cg * 16;
        soff[i] = (uint32_t)(row * 128 + ((cg ^ (row & 7)) << 4));
    }

    // persistent exp accumulators: n = n_off + ing*8 + (lane&3)*2 + j
    float sn[4][2];
    #pragma unroll
    for (int ing = 0; ing < 4; ing++) { sn[ing][0] = 0.0f; sn[ing][1] = 0.0f; }

    float xnv[4][2];
    #pragma unroll
    for (int ing = 0; ing < 4; ing++)
        #pragma unroll
        for (int j = 0; j < 2; j++)
            xnv[ing][j] = g_xnorm[b_base + n_off + ing * 8 + (lane & 3) * 2 + j] * L2E;

    for (int kt = 0; kt < KSLICES; kt++) {
        const int k_base = (blockIdx.y * KSLICES + kt) * MTILE;
        const uint8_t* gA = g_phi8 + (uint64_t)k_base * Dn;

        float acc[4][4][4];
        #pragma unroll
        for (int i = 0; i < 4; i++)
            #pragma unroll
            for (int j = 0; j < 4; j++)
                #pragma unroll
                for (int r = 0; r < 4; r++) acc[i][j][r] = 0.0f;

        // prologue: stage chunks 0 and 1
        #pragma unroll
        for (int pc = 0; pc < 2; pc++) {
            const uint32_t st = Sbase + (uint32_t)pc * STAGE_BYTES;
            #pragma unroll
            for (int i = 0; i < 4; i++) {
                CP16(st + soff[i],          gA + srow[i] * Dn + pc * DK + sgo[i]);
                CP16(st + 16384u + soff[i], gB + srow[i] * Dn + pc * DK + sgo[i]);
            }
            CP_COMMIT();
        }

        for (int c = 0; c < NCHUNK; c++) {
            if (c < NCHUNK - 1) CP_WAIT(1); else CP_WAIT(0);
            __syncthreads();

            if (c + 2 < NCHUNK) {
                const uint32_t st = Sbase + (uint32_t)((c + 2) % STAGES) * STAGE_BYTES;
                const int d0 = (c + 2) * DK;
                #pragma unroll
                for (int i = 0; i < 4; i++) {
                    CP16(st + soff[i],          gA + srow[i] * Dn + d0 + sgo[i]);
                    CP16(st + 16384u + soff[i], gB + srow[i] * Dn + d0 + sgo[i]);
                }
                CP_COMMIT();
            }

            const uint32_t Ab = Sbase + (uint32_t)(c % STAGES) * STAGE_BYTES;
            const uint32_t Bb = Ab + 16384u;

            #pragma unroll
            for (int ks = 0; ks < 4; ks++) {
                uint32_t a[4][4];
                #pragma unroll
                for (int im = 0; im < 4; im++) {
                    const int arow = m_off + im * 16 + (lane & 15);
                    const int acg  = ks * 2 + (lane >> 4);
                    LDSM4(a[im][0], a[im][1], a[im][2], a[im][3],
                          Ab + (uint32_t)(arow * 128 + ((acg ^ (arow & 7)) << 4)));
                }
                uint32_t b[8];
                #pragma unroll
                for (int in_ = 0; in_ < 2; in_++) {
                    const int g    = lane >> 3;
                    const int nrow = n_off + in_ * 16 + ((g >> 1) << 3) + (lane & 7);
                    const int bcg  = ks * 2 + (g & 1);
                    LDSM4(b[in_ * 4 + 0], b[in_ * 4 + 1], b[in_ * 4 + 2], b[in_ * 4 + 3],
                          Bb + (uint32_t)(nrow * 128 + ((bcg ^ (nrow & 7)) << 4)));
                }
                #pragma unroll
                for (int im = 0; im < 4; im++)
                    #pragma unroll
                    for (int ing = 0; ing < 4; ing++)
                        MMA16832(acc[im][ing], a[im], b[ing * 2], b[ing * 2 + 1]);
            }
        }

        // per-slice epilogue: fold exp into sn
        float pnl[4], pnh[4];
        #pragma unroll
        for (int im = 0; im < 4; im++) {
            pnl[im] = g_phinorm[k_base + m_off + im * 16 + (lane >> 2)] * L2E;
            pnh[im] = g_phinorm[k_base + m_off + im * 16 + (lane >> 2) + 8] * L2E;
        }
        #pragma unroll
        for (int im = 0; im < 4; im++) {
            #pragma unroll
            for (int ing = 0; ing < 4; ing++) {
                #pragma unroll
                for (int j = 0; j < 2; j++) {
                    sn[ing][j] += exp2_fast(fmaf(SINV, acc[im][ing][j],     -(pnl[im] + xnv[ing][j])));
                    sn[ing][j] += exp2_fast(fmaf(SINV, acc[im][ing][2 + j], -(pnh[im] + xnv[ing][j])));
                }
            }
        }
        __syncthreads();   // all done with smem stages before next slice prologue
    }

    // reduce over the 8 m-lane groups (lane bits 2..4)
    #pragma unroll
    for (int off = 4; off < 32; off <<= 1)
        #pragma unroll
        for (int ing = 0; ing < 4; ing++)
            #pragma unroll
            for (int j = 0; j < 2; j++)
                sn[ing][j] += __shfl_xor_sync(0xffffffffu, sn[ing][j], off);

    if (lane < 4) {
        #pragma unroll
        for (int ing = 0; ing < 4; ing++)
            #pragma unroll
            for (int j = 0; j < 2; j++)
                atomicAdd(&g_colsum[b_base + n_off + ing * 8 + lane * 2 + j], sn[ing][j]);
    }

    // ---- last CTA of this b-slice finalizes its 128 columns ----
    __shared__ int is_last;
    __threadfence();
    if (t == 0) {
        const int old = atomicAdd(&g_cnt[blockIdx.x], 1);
        is_last = (old == (Kn / (MTILE * KSLICES)) - 1);
    }
    __syncthreads();
    if (is_last && t < NTILE) {
        float s = __logf(g_colsum[b_base + t] * (1.0f / (float)Kn) + 1e-9f)
                  * (1.0f / (float)Bn);
        #pragma unroll
        for (int off = 16; off > 0; off >>= 1)
            s += __shfl_xor_sync(0xffffffffu, s, off);
        if (lane == 0) atomicAdd(out, s);
    }
}

// ============================================================
extern "C" void kernel_launch(void* const* d_in, const int* in_sizes, int n_in,
                              void* d_out, int out_size)
{
    const float* x  = (const float*)d_in[0];
    const float* z  = (const float*)d_in[1];
    const float* W1 = (const float*)d_in[2];
    const float* b1 = (const float*)d_in[3];
    const float* W2 = (const float*)d_in[4];
    const float* b2 = (const float*)d_in[5];
    float* out = (float*)d_out;

    static int smem_set = 0;
    if (!smem_set) {
        cudaFuncSetAttribute(main_kernel, cudaFuncAttributeMaxDynamicSharedMemorySize,
                             STAGES * STAGE_BYTES);
        smem_set = 1;
    }

    prep_kernel<<<Bn / 8 + Kn, 256>>>(x, z, W1, b1, W2, b2, out);
    dim3 grid(Bn / NTILE, Kn / (MTILE * KSLICES));   // (128, 2)
    main_kernel<<<grid, 256, STAGES * STAGE_BYTES>>>(out);
}

// round 7
// speedup vs baseline: 1.2171x; 1.1187x over previous
#include <cuda_runtime.h>
#include <cuda_bf16.h>
#include <math.h>
#include <cstdint>

#define Bn 16384
#define Dn 1024
#define Kn 512
#define Ln 128
#define Hn 64

#define MTILE 128
#define NTILE 128
#define DK    128            // fp8 elems per chunk (128B rows)
#define NCHUNK (Dn / DK)     // 8
#define STAGES 3
#define STAGE_BYTES 32768u   // A(16KB) + B(16KB)

#define L2E 1.4426950408889634f
#define SCALE 16.0f
#define SINV (2.0f * L2E / (SCALE * SCALE))

// ---------------- scratch ----------------
__device__ uint8_t g_phi8[Kn * Dn];
__device__ uint8_t g_x8[Bn * Dn];
__device__ float g_phinorm[Kn];
__device__ float g_xnorm[Bn];
__device__ float g_colsum[Bn];
__device__ int   g_cnt[Bn / NTILE];

// ---------------- helpers ----------------
__device__ __forceinline__ uint32_t smem_u32(const void* p) {
    uint32_t a;
    asm("{ .reg .u64 t; cvta.to.shared.u64 t, %1; cvt.u32.u64 %0, t; }" : "=r"(a) : "l"(p));
    return a;
}

#define LDSM4(r0, r1, r2, r3, addr) \
    asm volatile("ldmatrix.sync.aligned.m8n8.x4.shared.b16 {%0,%1,%2,%3}, [%4];" \
                 : "=r"(r0), "=r"(r1), "=r"(r2), "=r"(r3) : "r"(addr))

#define MMA16832(d, a, b0, b1) \
    asm volatile("mma.sync.aligned.m16n8k32.row.col.f32.e4m3.e4m3.f32 " \
                 "{%0,%1,%2,%3}, {%4,%5,%6,%7}, {%8,%9}, {%0,%1,%2,%3};" \
                 : "+f"((d)[0]), "+f"((d)[1]), "+f"((d)[2]), "+f"((d)[3]) \
                 : "r"((a)[0]), "r"((a)[1]), "r"((a)[2]), "r"((a)[3]), \
                   "r"(b0), "r"(b1))

#define CP16(dst, src) \
    asm volatile("cp.async.cg.shared.global [%0], [%1], 16;" :: "r"(dst), "l"(src))
#define CP_COMMIT()  asm volatile("cp.async.commit_group;" ::: "memory")
#define CP_WAIT(n)   asm volatile("cp.async.wait_group %0;" :: "n"(n) : "memory")

__device__ __forceinline__ uint32_t pack_e4m3x4(float e0, float e1, float e2, float e3) {
    uint16_t lo, hi;
    asm("cvt.rn.satfinite.e4m3x2.f32 %0, %1, %2;" : "=h"(lo) : "f"(e1), "f"(e0));
    asm("cvt.rn.satfinite.e4m3x2.f32 %0, %1, %2;" : "=h"(hi) : "f"(e3), "f"(e2));
    return (uint32_t)lo | ((uint32_t)hi << 16);
}

// fast 2^t, FFMA-only. deg-4 poly on [-0.5, 0.5]
__device__ __forceinline__ float exp2_fast(float t) {
    t = fmaxf(t, -126.0f);
    const int   i = __float2int_rn(t);
    const float f = t - (float)i;
    float p = fmaf(0.0096181291f, f, 0.0555041087f);
    p = fmaf(p, f, 0.2402265069f);
    p = fmaf(p, f, 0.6931471806f);
    p = fmaf(p, f, 1.0f);
    return p * __int_as_float((i + 127) << 23);
}

// ============================================================
// Kernel 1 (prep): blocks [0, 2048) = x (warp per row);
//                  blocks [2048, 2048+Kn) = phi MLP
// ============================================================
__global__ __launch_bounds__(256) void prep_kernel(
    const float* __restrict__ x,  const float* __restrict__ z,
    const float* __restrict__ W1, const float* __restrict__ b1,
    const float* __restrict__ W2, const float* __restrict__ b2,
    float* __restrict__ out)
{
    const int t = threadIdx.x;

    if (blockIdx.x < Bn / 8) {
        const int lane = t & 31;
        const int b = blockIdx.x * 8 + (t >> 5);
        const float* xr = x + (uint64_t)b * Dn;
        uint8_t* xo = g_x8 + (uint64_t)b * Dn;
        float nrm = 0.0f;
        #pragma unroll
        for (int i = 0; i < 8; i++) {
            const float4 v = *reinterpret_cast<const float4*>(xr + i * 128 + lane * 4);
            *reinterpret_cast<uint32_t*>(xo + i * 128 + lane * 4) =
                pack_e4m3x4(v.x * SCALE, v.y * SCALE, v.z * SCALE, v.w * SCALE);
            nrm = fmaf(v.x, v.x, nrm);
            nrm = fmaf(v.y, v.y, nrm);
            nrm = fmaf(v.z, v.z, nrm);
            nrm = fmaf(v.w, v.w, nrm);
        }
        #pragma unroll
        for (int off = 16; off > 0; off >>= 1)
            nrm += __shfl_xor_sync(0xffffffffu, nrm, off);
        if (lane == 0) {
            g_xnorm[b] = nrm;
            g_colsum[b] = 0.0f;
            if (b < Bn / NTILE) g_cnt[b] = 0;
            if (b == 0) out[0] = 0.0f;
        }
    } else {
        __shared__ float zrow[Ln];
        __shared__ float hidden[Hn];
        __shared__ float red[256];
        const int k = blockIdx.x - Bn / 8;

        if (t < Ln) zrow[t] = z[k * Ln + t];
        __syncthreads();

        if (t < Hn) {
            float acc = b1[t];
            #pragma unroll 8
            for (int l = 0; l < Ln; l++)
                acc = fmaf(zrow[l], W1[l * Hn + t], acc);
            hidden[t] = fmaxf(acc, 0.0f);
        }
        __syncthreads();

        const int d0 = t * 4;
        float4 acc = make_float4(b2[d0], b2[d0 + 1], b2[d0 + 2], b2[d0 + 3]);
        #pragma unroll 8
        for (int h = 0; h < Hn; h++) {
            const float hv = hidden[h];
            const float4 w = *reinterpret_cast<const float4*>(W2 + h * Dn + d0);
            acc.x = fmaf(hv, w.x, acc.x);
            acc.y = fmaf(hv, w.y, acc.y);
            acc.z = fmaf(hv, w.z, acc.z);
            acc.w = fmaf(hv, w.w, acc.w);
        }
        *reinterpret_cast<uint32_t*>(g_phi8 + k * Dn + d0) =
            pack_e4m3x4(acc.x * SCALE, acc.y * SCALE, acc.z * SCALE, acc.w * SCALE);

        red[t] = acc.x * acc.x + acc.y * acc.y + acc.z * acc.z + acc.w * acc.w;
        __syncthreads();
        for (int s = 128; s > 0; s >>= 1) {
            if (t < s) red[t] += red[t + s];
            __syncthreads();
        }
        if (t == 0) g_phinorm[k] = red[0];
    }
}

// ============================================================
// Kernel 2 (main): fp8 mma GEMM 128x128, 3-stage cp.async,
//   hoisted XOR-swizzle addressing, fused exp epilogue
// ============================================================
__global__ __launch_bounds__(256, 2) void main_kernel(float* __restrict__ out)
{
    extern __shared__ char smem[];
    uint32_t Sraw = smem_u32(smem);
    const uint32_t Sal = (Sraw + 127u) & ~127u;   // 128B-aligned stage base

    const int t    = threadIdx.x;
    const int lane = t & 31;
    const int wid  = t >> 5;
    const int b_base = blockIdx.x * NTILE;
    const int k_base = blockIdx.y * MTILE;

    const int m_off = (wid & 1) * 64;
    const int n_off = (wid >> 1) * 32;

    const uint8_t* gA = g_phi8 + (uint64_t)k_base * Dn;
    const uint8_t* gB = g_x8   + (uint64_t)b_base * Dn;

    // ---- loop-invariant LDSM base offsets (within a stage) ----
    // addr(ks) = stage + base ^ (ks<<5); base bits5-6 hold (r&6)<<4
    uint32_t a_base[4], b_base2[2];
    {
        const int hi = lane >> 4;
        #pragma unroll
        for (int im = 0; im < 4; im++) {
            const int arow = m_off + im * 16 + (lane & 15);
            const int r = arow & 7;
            a_base[im] = (uint32_t)(arow * 128 + ((hi ^ (r & 1)) << 4) + ((r & 6) << 4));
        }
        const int g  = lane >> 3;
        const int rb = lane & 7;
        #pragma unroll
        for (int in_ = 0; in_ < 2; in_++) {
            const int nrow = n_off + in_ * 16 + ((g >> 1) << 3) + rb;
            b_base2[in_] = (uint32_t)(nrow * 128 + (((g & 1) ^ (rb & 1)) << 4) + ((rb & 6) << 4));
        }
    }

    // ---- staging map: 4 x 16B units per array per thread ----
    const uint8_t* pa[4];
    const uint8_t* pb[4];
    uint32_t soff[4];
    #pragma unroll
    for (int i = 0; i < 4; i++) {
        const int u = t + i * 256;
        const int row = u >> 3;
        const int cg  = u & 7;
        pa[i] = gA + row * Dn + cg * 16;
        pb[i] = gB + row * Dn + cg * 16;
        soff[i] = (uint32_t)(row * 128 + ((cg ^ (row & 7)) << 4));
    }

    float acc[4][4][4];
    #pragma unroll
    for (int i = 0; i < 4; i++)
        #pragma unroll
        for (int j = 0; j < 4; j++)
            #pragma unroll
            for (int r = 0; r < 4; r++) acc[i][j][r] = 0.0f;

    // prologue: stage chunks 0, 1
    #pragma unroll
    for (int pc = 0; pc < 2; pc++) {
        const uint32_t st = Sal + (uint32_t)pc * STAGE_BYTES;
        #pragma unroll
        for (int i = 0; i < 4; i++) {
            CP16(st + soff[i],          pa[i] + pc * DK);
            CP16(st + 16384u + soff[i], pb[i] + pc * DK);
        }
        CP_COMMIT();
    }

    for (int c = 0; c < NCHUNK; c++) {
        if (c < NCHUNK - 1) CP_WAIT(1); else CP_WAIT(0);
        __syncthreads();

        if (c + 2 < NCHUNK) {
            const uint32_t st = Sal + (uint32_t)((c + 2) % STAGES) * STAGE_BYTES;
            const int d0 = (c + 2) * DK;
            #pragma unroll
            for (int i = 0; i < 4; i++) {
                CP16(st + soff[i],          pa[i] + d0);
                CP16(st + 16384u + soff[i], pb[i] + d0);
            }
            CP_COMMIT();
        }

        const uint32_t As = Sal + (uint32_t)(c % STAGES) * STAGE_BYTES;
        uint32_t aaddr[4], baddr[2];
        #pragma unroll
        for (int im = 0; im < 4; im++) aaddr[im] = As + a_base[im];
        #pragma unroll
        for (int in_ = 0; in_ < 2; in_++) baddr[in_] = As + 16384u + b_base2[in_];

        #pragma unroll
        for (int ks = 0; ks < 4; ks++) {
            const uint32_t kx = (uint32_t)ks << 5;
            uint32_t a[4][4];
            #pragma unroll
            for (int im = 0; im < 4; im++)
                LDSM4(a[im][0], a[im][1], a[im][2], a[im][3], aaddr[im] ^ kx);
            uint32_t b[8];
            #pragma unroll
            for (int in_ = 0; in_ < 2; in_++)
                LDSM4(b[in_ * 4 + 0], b[in_ * 4 + 1], b[in_ * 4 + 2], b[in_ * 4 + 3],
                      baddr[in_] ^ kx);
            #pragma unroll
            for (int im = 0; im < 4; im++)
                #pragma unroll
                for (int ing = 0; ing < 4; ing++)
                    MMA16832(acc[im][ing], a[im], b[ing * 2], b[ing * 2 + 1]);
        }
    }

    // ---------------- fused epilogue ----------------
    float pnl[4], pnh[4];
    #pragma unroll
    for (int im = 0; im < 4; im++) {
        pnl[im] = g_phinorm[k_base + m_off + im * 16 + (lane >> 2)] * L2E;
        pnh[im] = g_phinorm[k_base + m_off + im * 16 + (lane >> 2) + 8] * L2E;
    }
    float xnv[4][2];
    #pragma unroll
    for (int ing = 0; ing < 4; ing++)
        #pragma unroll
        for (int j = 0; j < 2; j++)
            xnv[ing][j] = g_xnorm[b_base + n_off + ing * 8 + (lane & 3) * 2 + j] * L2E;

    float sn[4][2];
    #pragma unroll
    for (int ing = 0; ing < 4; ing++) { sn[ing][0] = 0.0f; sn[ing][1] = 0.0f; }

    #pragma unroll
    for (int im = 0; im < 4; im++) {
        #pragma unroll
        for (int ing = 0; ing < 4; ing++) {
            #pragma unroll
            for (int j = 0; j < 2; j++) {
                sn[ing][j] += exp2_fast(fmaf(SINV, acc[im][ing][j],     -(pnl[im] + xnv[ing][j])));
                sn[ing][j] += exp2_fast(fmaf(SINV, acc[im][ing][2 + j], -(pnh[im] + xnv[ing][j])));
            }
        }
    }
    #pragma unroll
    for (int off = 4; off < 32; off <<= 1)
        #pragma unroll
        for (int ing = 0; ing < 4; ing++)
            #pragma unroll
            for (int j = 0; j < 2; j++)
                sn[ing][j] += __shfl_xor_sync(0xffffffffu, sn[ing][j], off);

    if (lane < 4) {
        #pragma unroll
        for (int ing = 0; ing < 4; ing++)
            #pragma unroll
            for (int j = 0; j < 2; j++)
                atomicAdd(&g_colsum[b_base + n_off + ing * 8 + lane * 2 + j], sn[ing][j]);
    }

    // ---- last CTA of this b-slice finalizes its 128 columns ----
    __shared__ int is_last;
    __threadfence();
    if (t == 0) {
        const int old = atomicAdd(&g_cnt[blockIdx.x], 1);
        is_last = (old == (Kn / MTILE) - 1);
    }
    __syncthreads();
    if (is_last && t < NTILE) {
        float s = __logf(g_colsum[b_base + t] * (1.0f / (float)Kn) + 1e-9f)
                  * (1.0f / (float)Bn);
        #pragma unroll
        for (int off = 16; off > 0; off >>= 1)
            s += __shfl_xor_sync(0xffffffffu, s, off);
        if (lane == 0) atomicAdd(out, s);
    }
}

// ============================================================
extern "C" void kernel_launch(void* const* d_in, const int* in_sizes, int n_in,
                              void* d_out, int out_size)
{
    const float* x  = (const float*)d_in[0];
    const float* z  = (const float*)d_in[1];
    const float* W1 = (const float*)d_in[2];
    const float* b1 = (const float*)d_in[3];
    const float* W2 = (const float*)d_in[4];
    const float* b2 = (const float*)d_in[5];
    float* out = (float*)d_out;

    static int smem_set = 0;
    if (!smem_set) {
        cudaFuncSetAttribute(main_kernel, cudaFuncAttributeMaxDynamicSharedMemorySize,
                             STAGES * STAGE_BYTES + 128);
        smem_set = 1;
    }

    prep_kernel<<<Bn / 8 + Kn, 256>>>(x, z, W1, b1, W2, b2, out);
    dim3 grid(Bn / NTILE, Kn / MTILE);   // (128, 4)
    main_kernel<<<grid, 256, STAGES * STAGE_BYTES + 128>>>(out);
}

// round 8
// speedup vs baseline: 1.2269x; 1.0080x over previous
#include <cuda_runtime.h>
#include <cuda_bf16.h>
#include <math.h>
#include <cstdint>

#define Bn 16384
#define Dn 1024
#define Kn 512
#define Ln 128
#define Hn 64

#define MTILE 128
#define NTILE 128
#define DK    128            // fp8 elems per chunk (128B rows)
#define NCHUNK (Dn / DK)     // 8
#define STAGES 3
#define STAGE_BYTES 32768u   // A(16KB) + B(16KB)

// chunk-major strides (bytes per chunk block)
#define CHB_X   ((uint64_t)Bn * 128)   // 2 MB
#define CHB_PHI ((uint64_t)Kn * 128)   // 64 KB

#define L2E 1.4426950408889634f
#define SCALE 16.0f
#define SINV (2.0f * L2E / (SCALE * SCALE))

// ---------------- scratch (chunk-major, PRE-SWIZZLED) ----------------
// layout: [chunk c][row][128 bytes], 16B groups within a row permuted by
// cg' = cg ^ (row & 7)  — i.e. the ldmatrix swizzle is baked in at prep time.
__device__ uint8_t g_phi8[Kn * Dn];
__device__ uint8_t g_x8[Bn * Dn];
__device__ float g_phinorm[Kn];
__device__ float g_xnorm[Bn];
__device__ float g_colsum[Bn];
__device__ int   g_cnt[Bn / NTILE];

// ---------------- helpers ----------------
__device__ __forceinline__ uint32_t smem_u32(const void* p) {
    uint32_t a;
    asm("{ .reg .u64 t; cvta.to.shared.u64 t, %1; cvt.u32.u64 %0, t; }" : "=r"(a) : "l"(p));
    return a;
}

#define LDSM4(r0, r1, r2, r3, addr) \
    asm volatile("ldmatrix.sync.aligned.m8n8.x4.shared.b16 {%0,%1,%2,%3}, [%4];" \
                 : "=r"(r0), "=r"(r1), "=r"(r2), "=r"(r3) : "r"(addr))

#define MMA16832(d, a, b0, b1) \
    asm volatile("mma.sync.aligned.m16n8k32.row.col.f32.e4m3.e4m3.f32 " \
                 "{%0,%1,%2,%3}, {%4,%5,%6,%7}, {%8,%9}, {%0,%1,%2,%3};" \
                 : "+f"((d)[0]), "+f"((d)[1]), "+f"((d)[2]), "+f"((d)[3]) \
                 : "r"((a)[0]), "r"((a)[1]), "r"((a)[2]), "r"((a)[3]), \
                   "r"(b0), "r"(b1))

#define CP16(dst, src) \
    asm volatile("cp.async.cg.shared.global [%0], [%1], 16;" :: "r"(dst), "l"(src))
#define CP_COMMIT()  asm volatile("cp.async.commit_group;" ::: "memory")
#define CP_WAIT(n)   asm volatile("cp.async.wait_group %0;" :: "n"(n) : "memory")

__device__ __forceinline__ uint32_t pack_e4m3x4(float e0, float e1, float e2, float e3) {
    uint16_t lo, hi;
    asm("cvt.rn.satfinite.e4m3x2.f32 %0, %1, %2;" : "=h"(lo) : "f"(e1), "f"(e0));
    asm("cvt.rn.satfinite.e4m3x2.f32 %0, %1, %2;" : "=h"(hi) : "f"(e3), "f"(e2));
    return (uint32_t)lo | ((uint32_t)hi << 16);
}

// fast 2^t, FFMA-only. deg-4 poly on [-0.5, 0.5]
__device__ __forceinline__ float exp2_fast(float t) {
    t = fmaxf(t, -126.0f);
    const int   i = __float2int_rn(t);
    const float f = t - (float)i;
    float p = fmaf(0.0096181291f, f, 0.0555041087f);
    p = fmaf(p, f, 0.2402265069f);
    p = fmaf(p, f, 0.6931471806f);
    p = fmaf(p, f, 1.0f);
    return p * __int_as_float((i + 127) << 23);
}

// ============================================================
// Kernel 1 (prep): blocks [0, 2048) = x (warp per row);
//                  blocks [2048, 2048+Kn) = phi MLP
// Both write CHUNK-MAJOR PRE-SWIZZLED fp8.
// ============================================================
__global__ __launch_bounds__(256) void prep_kernel(
    const float* __restrict__ x,  const float* __restrict__ z,
    const float* __restrict__ W1, const float* __restrict__ b1,
    const float* __restrict__ W2, const float* __restrict__ b2,
    float* __restrict__ out)
{
    const int t = threadIdx.x;

    if (blockIdx.x < Bn / 8) {
        const int lane = t & 31;
        const int b = blockIdx.x * 8 + (t >> 5);
        const float* xr = x + (uint64_t)b * Dn;
        // swizzled in-row byte offset for this lane's 4 bytes
        const uint32_t rowoff = ((((lane >> 2) ^ (b & 7)) << 4) | ((lane & 3) << 2));
        uint8_t* xo = g_x8 + (uint64_t)b * 128 + rowoff;
        float nrm = 0.0f;
        #pragma unroll
        for (int i = 0; i < 8; i++) {
            const float4 v = *reinterpret_cast<const float4*>(xr + i * 128 + lane * 4);
            *reinterpret_cast<uint32_t*>(xo + i * CHB_X) =
                pack_e4m3x4(v.x * SCALE, v.y * SCALE, v.z * SCALE, v.w * SCALE);
            nrm = fmaf(v.x, v.x, nrm);
            nrm = fmaf(v.y, v.y, nrm);
            nrm = fmaf(v.z, v.z, nrm);
            nrm = fmaf(v.w, v.w, nrm);
        }
        #pragma unroll
        for (int off = 16; off > 0; off >>= 1)
            nrm += __shfl_xor_sync(0xffffffffu, nrm, off);
        if (lane == 0) {
            g_xnorm[b] = nrm;
            g_colsum[b] = 0.0f;
            if (b < Bn / NTILE) g_cnt[b] = 0;
            if (b == 0) out[0] = 0.0f;
        }
    } else {
        __shared__ float zrow[Ln];
        __shared__ float hidden[Hn];
        __shared__ float red[256];
        const int k = blockIdx.x - Bn / 8;

        if (t < Ln) zrow[t] = z[k * Ln + t];
        __syncthreads();

        if (t < Hn) {
            float acc = b1[t];
            #pragma unroll 8
            for (int l = 0; l < Ln; l++)
                acc = fmaf(zrow[l], W1[l * Hn + t], acc);
            hidden[t] = fmaxf(acc, 0.0f);
        }
        __syncthreads();

        const int d0 = t * 4;
        float4 acc = make_float4(b2[d0], b2[d0 + 1], b2[d0 + 2], b2[d0 + 3]);
        #pragma unroll 8
        for (int h = 0; h < Hn; h++) {
            const float hv = hidden[h];
            const float4 w = *reinterpret_cast<const float4*>(W2 + h * Dn + d0);
            acc.x = fmaf(hv, w.x, acc.x);
            acc.y = fmaf(hv, w.y, acc.y);
            acc.z = fmaf(hv, w.z, acc.z);
            acc.w = fmaf(hv, w.w, acc.w);
        }
        {
            const int chunk = t >> 5;
            const uint32_t rowoff = (((((t >> 2) & 7) ^ (k & 7)) << 4) | ((t & 3) << 2));
            *reinterpret_cast<uint32_t*>(
                g_phi8 + (uint64_t)chunk * CHB_PHI + (uint64_t)k * 128 + rowoff) =
                pack_e4m3x4(acc.x * SCALE, acc.y * SCALE, acc.z * SCALE, acc.w * SCALE);
        }

        red[t] = acc.x * acc.x + acc.y * acc.y + acc.z * acc.z + acc.w * acc.w;
        __syncthreads();
        for (int s = 128; s > 0; s >>= 1) {
            if (t < s) red[t] += red[t + s];
            __syncthreads();
        }
        if (t == 0) g_phinorm[k] = red[0];
    }
}

// ============================================================
// Kernel 2 (main): fp8 mma GEMM 128x128, 3-stage cp.async from
//   contiguous pre-swizzled tiles, fused exp epilogue
// ============================================================
__global__ __launch_bounds__(256, 2) void main_kernel(float* __restrict__ out)
{
    extern __shared__ char smem[];
    uint32_t Sraw = smem_u32(smem);
    const uint32_t Sal = (Sraw + 127u) & ~127u;

    const int t    = threadIdx.x;
    const int lane = t & 31;
    const int wid  = t >> 5;
    const int b_base = blockIdx.x * NTILE;
    const int k_base = blockIdx.y * MTILE;

    const int m_off = (wid & 1) * 64;
    const int n_off = (wid >> 1) * 32;

    // contiguous tile sources (chunk-major): advance by CHB per chunk
    const uint8_t* srcA = g_phi8 + (uint64_t)k_base * 128 + (uint32_t)t * 16;
    const uint8_t* srcB = g_x8   + (uint64_t)b_base * 128 + (uint32_t)t * 16;
    const uint32_t doff = (uint32_t)t * 16;

    // ---- loop-invariant LDSM base offsets (within a stage) ----
    uint32_t a_base[4], b_base2[2];
    {
        const int hi = lane >> 4;
        #pragma unroll
        for (int im = 0; im < 4; im++) {
            const int arow = m_off + im * 16 + (lane & 15);
            const int r = arow & 7;
            a_base[im] = (uint32_t)(arow * 128 + ((hi ^ (r & 1)) << 4) + ((r & 6) << 4));
        }
        const int g  = lane >> 3;
        const int rb = lane & 7;
        #pragma unroll
        for (int in_ = 0; in_ < 2; in_++) {
            const int nrow = n_off + in_ * 16 + ((g >> 1) << 3) + rb;
            b_base2[in_] = (uint32_t)(nrow * 128 + (((g & 1) ^ (rb & 1)) << 4) + ((rb & 6) << 4));
        }
    }

    float acc[4][4][4];
    #pragma unroll
    for (int i = 0; i < 4; i++)
        #pragma unroll
        for (int j = 0; j < 4; j++)
            #pragma unroll
            for (int r = 0; r < 4; r++) acc[i][j][r] = 0.0f;

    // prologue: stage chunks 0, 1
    #pragma unroll
    for (int pc = 0; pc < 2; pc++) {
        const uint32_t st = Sal + (uint32_t)pc * STAGE_BYTES;
        const uint8_t* sa = srcA + pc * CHB_PHI;
        const uint8_t* sb = srcB + pc * CHB_X;
        #pragma unroll
        for (int i = 0; i < 4; i++) {
            CP16(st + doff + i * 4096u,           sa + i * 4096);
            CP16(st + 16384u + doff + i * 4096u,  sb + i * 4096);
        }
        CP_COMMIT();
    }

    for (int c = 0; c < NCHUNK; c++) {
        if (c < NCHUNK - 1) CP_WAIT(1); else CP_WAIT(0);
        __syncthreads();

        if (c + 2 < NCHUNK) {
            const uint32_t st = Sal + (uint32_t)((c + 2) % STAGES) * STAGE_BYTES;
            const uint8_t* sa = srcA + (c + 2) * CHB_PHI;
            const uint8_t* sb = srcB + (uint64_t)(c + 2) * CHB_X;
            #pragma unroll
            for (int i = 0; i < 4; i++) {
                CP16(st + doff + i * 4096u,          sa + i * 4096);
                CP16(st + 16384u + doff + i * 4096u, sb + i * 4096);
            }
            CP_COMMIT();
        }

        const uint32_t As = Sal + (uint32_t)(c % STAGES) * STAGE_BYTES;
        uint32_t aaddr[4], baddr[2];
        #pragma unroll
        for (int im = 0; im < 4; im++) aaddr[im] = As + a_base[im];
        #pragma unroll
        for (int in_ = 0; in_ < 2; in_++) baddr[in_] = As + 16384u + b_base2[in_];

        #pragma unroll
        for (int ks = 0; ks < 4; ks++) {
            const uint32_t kx = (uint32_t)ks << 5;
            uint32_t a[4][4];
            #pragma unroll
            for (int im = 0; im < 4; im++)
                LDSM4(a[im][0], a[im][1], a[im][2], a[im][3], aaddr[im] ^ kx);
            uint32_t b[8];
            #pragma unroll
            for (int in_ = 0; in_ < 2; in_++)
                LDSM4(b[in_ * 4 + 0], b[in_ * 4 + 1], b[in_ * 4 + 2], b[in_ * 4 + 3],
                      baddr[in_] ^ kx);
            #pragma unroll
            for (int im = 0; im < 4; im++)
                #pragma unroll
                for (int ing = 0; ing < 4; ing++)
                    MMA16832(acc[im][ing], a[im], b[ing * 2], b[ing * 2 + 1]);
        }
    }

    // ---------------- fused epilogue ----------------
    float pnl[4], pnh[4];
    #pragma unroll
    for (int im = 0; im < 4; im++) {
        pnl[im] = g_phinorm[k_base + m_off + im * 16 + (lane >> 2)] * L2E;
        pnh[im] = g_phinorm[k_base + m_off + im * 16 + (lane >> 2) + 8] * L2E;
    }
    float xnv[4][2];
    #pragma unroll
    for (int ing = 0; ing < 4; ing++)
        #pragma unroll
        for (int j = 0; j < 2; j++)
            xnv[ing][j] = g_xnorm[b_base + n_off + ing * 8 + (lane & 3) * 2 + j] * L2E;

    float sn[4][2];
    #pragma unroll
    for (int ing = 0; ing < 4; ing++) { sn[ing][0] = 0.0f; sn[ing][1] = 0.0f; }

    #pragma unroll
    for (int im = 0; im < 4; im++) {
        #pragma unroll
        for (int ing = 0; ing < 4; ing++) {
            #pragma unroll
            for (int j = 0; j < 2; j++) {
                sn[ing][j] += exp2_fast(fmaf(SINV, acc[im][ing][j],     -(pnl[im] + xnv[ing][j])));
                sn[ing][j] += exp2_fast(fmaf(SINV, acc[im][ing][2 + j], -(pnh[im] + xnv[ing][j])));
            }
        }
    }
    #pragma unroll
    for (int off = 4; off < 32; off <<= 1)
        #pragma unroll
        for (int ing = 0; ing < 4; ing++)
            #pragma unroll
            for (int j = 0; j < 2; j++)
                sn[ing][j] += __shfl_xor_sync(0xffffffffu, sn[ing][j], off);

    if (lane < 4) {
        #pragma unroll
        for (int ing = 0; ing < 4; ing++)
            #pragma unroll
            for (int j = 0; j < 2; j++)
                atomicAdd(&g_colsum[b_base + n_off + ing * 8 + lane * 2 + j], sn[ing][j]);
    }

    // ---- last CTA of this b-slice finalizes its 128 columns ----
    __shared__ int is_last;
    __threadfence();
    if (t == 0) {
        const int old = atomicAdd(&g_cnt[blockIdx.x], 1);
        is_last = (old == (Kn / MTILE) - 1);
    }
    __syncthreads();
    if (is_last && t < NTILE) {
        float s = __logf(g_colsum[b_base + t] * (1.0f / (float)Kn) + 1e-9f)
                  * (1.0f / (float)Bn);
        #pragma unroll
        for (int off = 16; off > 0; off >>= 1)
            s += __shfl_xor_sync(0xffffffffu, s, off);
        if (lane == 0) atomicAdd(out, s);
    }
}

// ============================================================
extern "C" void kernel_launch(void* const* d_in, const int* in_sizes, int n_in,
                              void* d_out, int out_size)
{
    const float* x  = (const float*)d_in[0];
    const float* z  = (const float*)d_in[1];
    const float* W1 = (const float*)d_in[2];
    const float* b1 = (const float*)d_in[3];
    const float* W2 = (const float*)d_in[4];
    const float* b2 = (const float*)d_in[5];
    float* out = (float*)d_out;

    static int smem_set = 0;
    if (!smem_set) {
        cudaFuncSetAttribute(main_kernel, cudaFuncAttributeMaxDynamicSharedMemorySize,
                             STAGES * STAGE_BYTES + 128);
        smem_set = 1;
    }

    prep_kernel<<<Bn / 8 + Kn, 256>>>(x, z, W1, b1, W2, b2, out);
    dim3 grid(Bn / NTILE, Kn / MTILE);   // (128, 4)
    main_kernel<<<grid, 256, STAGES * STAGE_BYTES + 128>>>(out);
}